// round 1
// baseline (speedup 1.0000x reference)
#include <cuda_runtime.h>
#include <cuda_bf16.h>
#include <cstdint>

// Problem constants
#define BB 32
#define NN 400
#define TT 315
#define DD 512
#define HH 256
#define BT (BB*TT)          // 10080
#define NT (NN*TT)          // 126000

// ---------------- scratch (static device globals; no allocation) -------------
__device__ float g_WhT[HH*2*DD];        // [256][1024]
__device__ float g_TAT[TT*DD];          // [315][512]
__device__ float g_S[BB*NN*TT];         // [32][400][315]
__device__ float g_txh[TT*HH];          // [315][256]
__device__ float g_mv[2*BB];            // mean, rstd per batch
__device__ float g_fT[BB*DD*NN];        // [32][512][400]
__device__ float g_s1T[BB*TT*NN];       // [32][315][400]
__device__ float g_f1[BB*TT*DD];        // [32][315][512]
__device__ float g_H[BB*TT*HH];         // [32][315][256]

// ---------------- generic fp32 NT GEMM:  C[m,n] = sum_k A[m,k]*B[n,k] --------
// EPI==1: C = relu(acc + aux[(m%auxT)*N + n] + bias[n])
template<int EPI>
__global__ void gemm_nt(
    int M, int N, int K,
    const float* __restrict__ A, int lda, long long sA,
    const float* __restrict__ B, int ldb, long long sB,
    float* __restrict__ C, int ldc, long long sC,
    const float* __restrict__ aux, const float* __restrict__ bias, int auxT)
{
    const int BM = 64, BN = 64, BK = 16;
    __shared__ float As[BK][BM + 4];
    __shared__ float Bs[BK][BN + 4];

    A += (long long)blockIdx.z * sA;
    B += (long long)blockIdx.z * sB;
    C += (long long)blockIdx.z * sC;

    int m0 = blockIdx.y * BM, n0 = blockIdx.x * BN;
    int tid = threadIdx.x;
    int tx = tid & 15, ty = tid >> 4;

    int lr = tid >> 2;          // 0..63 row-in-tile for loads
    int lk = (tid & 3) * 4;     // 0,4,8,12

    float acc[4][4];
    #pragma unroll
    for (int i = 0; i < 4; i++)
        #pragma unroll
        for (int j = 0; j < 4; j++) acc[i][j] = 0.f;

    for (int k0 = 0; k0 < K; k0 += BK) {
        int gm = m0 + lr;
        float4 va = make_float4(0.f, 0.f, 0.f, 0.f);
        if (gm < M) va = *(const float4*)(A + (size_t)gm * lda + k0 + lk);
        As[lk + 0][lr] = va.x; As[lk + 1][lr] = va.y;
        As[lk + 2][lr] = va.z; As[lk + 3][lr] = va.w;

        int gn = n0 + lr;
        float4 vb = make_float4(0.f, 0.f, 0.f, 0.f);
        if (gn < N) vb = *(const float4*)(B + (size_t)gn * ldb + k0 + lk);
        Bs[lk + 0][lr] = vb.x; Bs[lk + 1][lr] = vb.y;
        Bs[lk + 2][lr] = vb.z; Bs[lk + 3][lr] = vb.w;

        __syncthreads();
        #pragma unroll
        for (int kk = 0; kk < BK; kk++) {
            float a[4], b[4];
            *(float4*)a = *(const float4*)&As[kk][ty * 4];
            *(float4*)b = *(const float4*)&Bs[kk][tx * 4];
            #pragma unroll
            for (int i = 0; i < 4; i++)
                #pragma unroll
                for (int j = 0; j < 4; j++)
                    acc[i][j] += a[i] * b[j];
        }
        __syncthreads();
    }

    #pragma unroll
    for (int i = 0; i < 4; i++) {
        int gm = m0 + ty * 4 + i;
        if (gm >= M) continue;
        #pragma unroll
        for (int j = 0; j < 4; j++) {
            int gn = n0 + tx * 4 + j;
            if (gn >= N) continue;
            float val = acc[i][j];
            if (EPI == 1) {
                val += aux[(size_t)(gm % auxT) * N + gn] + bias[gn];
                val = fmaxf(val, 0.f);
            }
            C[(size_t)gm * ldc + gn] = val;
        }
    }
}

// ---------------- generic 32x32 tiled transpose: out[c][r] = in[r][c] --------
__global__ void transpose_k(const float* __restrict__ in, float* __restrict__ out,
                            int R, int C, long long sIn, long long sOut)
{
    __shared__ float tile[32][33];
    const float* inp = in + (long long)blockIdx.z * sIn;
    float* outp = out + (long long)blockIdx.z * sOut;
    int c0 = blockIdx.x * 32, r0 = blockIdx.y * 32;
    int x = threadIdx.x, y = threadIdx.y;
    #pragma unroll
    for (int j = 0; j < 32; j += 8) {
        int r = r0 + y + j, c = c0 + x;
        tile[y + j][x] = (r < R && c < C) ? inp[(size_t)r * C + c] : 0.f;
    }
    __syncthreads();
    #pragma unroll
    for (int j = 0; j < 32; j += 8) {
        int c = c0 + y + j, r = r0 + x;
        if (c < C && r < R) outp[(size_t)c * R + r] = tile[x][y + j];
    }
}

// ---------------- per-batch instance-norm stats ------------------------------
__global__ void stats_k(const float* __restrict__ s, float* __restrict__ mv)
{
    int b = blockIdx.x;
    const float* sb = s + (size_t)b * NT;
    float sum = 0.f, sq = 0.f;
    for (int i = threadIdx.x; i < NT; i += 256) {
        float x = sb[i];
        sum += x; sq += x * x;
    }
    __shared__ float ssum[256], ssq[256];
    ssum[threadIdx.x] = sum; ssq[threadIdx.x] = sq;
    __syncthreads();
    for (int o = 128; o > 0; o >>= 1) {
        if (threadIdx.x < o) {
            ssum[threadIdx.x] += ssum[threadIdx.x + o];
            ssq[threadIdx.x]  += ssq[threadIdx.x + o];
        }
        __syncthreads();
    }
    if (threadIdx.x == 0) {
        float m = ssum[0] / (float)NT;
        float var = ssq[0] / (float)NT - m * m;
        mv[2 * b] = m;
        mv[2 * b + 1] = rsqrtf(var + 1e-5f);
    }
}

// ---------------- Sinkhorn: 4-CTA cluster per batch, E resident in SMEM ------
// linear-domain factored form: iterate  u = 1/(E v),  v = 1/(E^T u)
#define SK_NW 8
#define SK_THREADS 256
#define RPC 100            // rows per CTA (400/4)
#define TP  317            // padded row stride (317 % 32 = 29, gcd(29,32)=1)

// smem float offsets
#define OFF_E    0
#define OFF_V    (RPC*TP)                 // 31700
#define OFF_U    (OFF_V + 320)            // 32020
#define OFF_WACC (OFF_U + 128)            // 32148
#define OFF_RECV (OFF_WACC + SK_NW*TP)    // 34684
#define SK_FLOATS (OFF_RECV + 2*4*TP)     // 37220
#define SK_SMEM  (SK_FLOATS*4)            // 148880 bytes

__global__ void __cluster_dims__(4, 1, 1) sinkhorn_kernel(
    const float* __restrict__ s, const float* __restrict__ gamma,
    const float* __restrict__ beta, const float* __restrict__ mv,
    float* __restrict__ s1T)
{
    extern __shared__ float sm[];
    float* E    = sm + OFF_E;      // [RPC][TP]
    float* vS   = sm + OFF_V;      // [315]
    float* uS   = sm + OFF_U;      // [100]
    float* wacc = sm + OFF_WACC;   // [8][TP]
    float* recv = sm + OFF_RECV;   // [2][4][TP]

    int b = blockIdx.x >> 2;
    int rank = blockIdx.x & 3;
    int tid = threadIdx.x, wid = tid >> 5, lane = tid & 31;
    int rowbase = rank * RPC;

    float m = mv[2 * b], rstd = mv[2 * b + 1];
    float g = gamma[0] * rstd, be = beta[0];
    const float* sb = s + (size_t)b * NT + (size_t)rowbase * TT;

    // load slab, normalize + exp
    for (int i = tid; i < RPC * TT; i += SK_THREADS) {
        int r = i / TT, c = i - r * TT;
        E[r * TP + c] = __expf(g * (sb[i] - m) + be);
    }
    for (int c = tid; c < TT; c += SK_THREADS) vS[c] = 1.f;
    __syncthreads();

    for (int it = 0; it < 100; ++it) {
        int par = it & 1;

        // --- row phase: u = 1/(E v); fused column-partial accumulation -------
        float vv[10];
        #pragma unroll
        for (int k = 0; k < 10; k++) {
            int c = lane + 32 * k;
            vv[k] = (c < TT) ? vS[c] : 0.f;
        }
        float cacc[10];
        #pragma unroll
        for (int k = 0; k < 10; k++) cacc[k] = 0.f;

        for (int r = wid; r < RPC; r += SK_NW) {
            const float* Er = E + r * TP;
            float e[10];
            float dot = 0.f;
            #pragma unroll
            for (int k = 0; k < 10; k++) {
                int c = lane + 32 * k;
                e[k] = (c < TT) ? Er[c] : 0.f;
                dot += e[k] * vv[k];
            }
            #pragma unroll
            for (int o = 16; o > 0; o >>= 1)
                dot += __shfl_xor_sync(0xffffffffu, dot, o);
            float uu = 1.f / dot;
            if (lane == 0) uS[r] = uu;
            #pragma unroll
            for (int k = 0; k < 10; k++) cacc[k] += uu * e[k];
        }
        #pragma unroll
        for (int k = 0; k < 10; k++) {
            int c = lane + 32 * k;
            if (c < TT) wacc[wid * TP + c] = cacc[k];
        }
        __syncthreads();

        // --- CTA-level column partial + broadcast to all 4 cluster CTAs ------
        for (int c = tid; c < TT; c += SK_THREADS) {
            float p = 0.f;
            #pragma unroll
            for (int w = 0; w < SK_NW; w++) p += wacc[w * TP + c];
            float* dst = recv + (par * 4 + rank) * TP + c;
            uint32_t laddr = (uint32_t)__cvta_generic_to_shared(dst);
            #pragma unroll
            for (int cta = 0; cta < 4; cta++) {
                uint32_t raddr;
                asm volatile("mapa.shared::cluster.u32 %0, %1, %2;"
                             : "=r"(raddr) : "r"(laddr), "r"(cta));
                asm volatile("st.shared::cluster.f32 [%0], %1;"
                             :: "r"(raddr), "f"(p) : "memory");
            }
        }
        // cluster barrier (arrive has release, wait has acquire semantics)
        asm volatile("barrier.cluster.arrive.aligned;" ::: "memory");
        asm volatile("barrier.cluster.wait.aligned;" ::: "memory");

        // --- col phase: v = 1/(sum of 4 partials) ---------------------------
        for (int c = tid; c < TT; c += SK_THREADS) {
            float sum = recv[(par * 4 + 0) * TP + c] + recv[(par * 4 + 1) * TP + c]
                      + recv[(par * 4 + 2) * TP + c] + recv[(par * 4 + 3) * TP + c];
            vS[c] = 1.f / sum;
        }
        __syncthreads();
    }

    // --- epilogue: s1T[b][t][rowbase+n] = E[n][t]*u[n]*v[t] ------------------
    float* outp = s1T + (size_t)b * TT * NN;
    for (int t = wid; t < TT; t += SK_NW) {
        float vt = vS[t];
        #pragma unroll
        for (int j = 0; j < 4; j++) {
            int n = lane + 32 * j;
            if (n < RPC)
                outp[(size_t)t * NN + rowbase + n] = E[n * TP + t] * uS[n] * vt;
        }
    }
}

// ---------------- final head: pred[bt] = dot(h[bt,:], Wo) + bo ---------------
__global__ void final_head(const float* __restrict__ h, const float* __restrict__ Wo,
                           const float* __restrict__ bo, float* __restrict__ out)
{
    int row = blockIdx.x * 8 + (threadIdx.x >> 5);
    int lane = threadIdx.x & 31;
    if (row >= BT) return;
    const float* hr = h + (size_t)row * HH;
    float acc = 0.f;
    #pragma unroll
    for (int k = 0; k < HH / 32; k++)
        acc += hr[lane + 32 * k] * Wo[lane + 32 * k];
    #pragma unroll
    for (int o = 16; o > 0; o >>= 1)
        acc += __shfl_xor_sync(0xffffffffu, acc, o);
    if (lane == 0) out[row] = acc + bo[0];
}

// ---------------- launcher ---------------------------------------------------
extern "C" void kernel_launch(void* const* d_in, const int* in_sizes, int n_in,
                              void* d_out, int out_size)
{
    const float* features = (const float*)d_in[0];
    const float* text     = (const float*)d_in[1];
    const float* Amat     = (const float*)d_in[2];
    const float* gamma    = (const float*)d_in[3];
    const float* beta     = (const float*)d_in[4];
    const float* Wh       = (const float*)d_in[5];
    const float* bh       = (const float*)d_in[6];
    const float* Wo       = (const float*)d_in[7];
    const float* bo       = (const float*)d_in[8];
    float* out = (float*)d_out;

    float *WhT, *TAT, *S, *txh, *mv, *fT, *s1T, *f1, *Hb;
    cudaGetSymbolAddress((void**)&WhT, g_WhT);
    cudaGetSymbolAddress((void**)&TAT, g_TAT);
    cudaGetSymbolAddress((void**)&S,   g_S);
    cudaGetSymbolAddress((void**)&txh, g_txh);
    cudaGetSymbolAddress((void**)&mv,  g_mv);
    cudaGetSymbolAddress((void**)&fT,  g_fT);
    cudaGetSymbolAddress((void**)&s1T, g_s1T);
    cudaGetSymbolAddress((void**)&f1,  g_f1);
    cudaGetSymbolAddress((void**)&Hb,  g_H);

    cudaFuncSetAttribute(sinkhorn_kernel,
                         cudaFuncAttributeMaxDynamicSharedMemorySize, SK_SMEM);

    dim3 tb(32, 8);

    // 1) WhT[h][c] = Wh[c][h]   (1024x256 -> 256x1024)
    transpose_k<<<dim3(8, 32, 1), tb>>>(Wh, WhT, 2 * DD, HH, 0, 0);

    // 2) TAT[t][d] = sum_e text[t,e]*A[d,e]
    gemm_nt<0><<<dim3(8, 5, 1), 256>>>(TT, DD, DD,
        text, DD, 0, Amat, DD, 0, TAT, DD, 0, nullptr, nullptr, 1);

    // 3) S[bn][t] = sum_d features[bn,d]*TAT[t,d]
    gemm_nt<0><<<dim3(5, 200, 1), 256>>>(BB * NN, TT, DD,
        features, DD, 0, TAT, DD, 0, S, TT, 0, nullptr, nullptr, 1);

    // 4) txh[t][h] = sum_d text[t,d]*Wh[512+d,h]
    gemm_nt<0><<<dim3(4, 5, 1), 256>>>(TT, HH, DD,
        text, DD, 0, WhT + DD, 2 * DD, 0, txh, HH, 0, nullptr, nullptr, 1);

    // 5) instance-norm stats per batch
    stats_k<<<BB, 256>>>(S, mv);

    // 6) fT[b][d][n] = features[b][n][d]
    transpose_k<<<dim3(16, 13, BB), tb>>>(features, fT, NN, DD,
                                          (long long)NN * DD, (long long)DD * NN);

    // 7) Sinkhorn (4-CTA clusters, 1 cluster per batch slab set)
    sinkhorn_kernel<<<BB * 4, SK_THREADS, SK_SMEM>>>(S, gamma, beta, mv, s1T);

    // 8) f1[b][t][d] = sum_n s1T[b][t][n]*fT[b][d][n]
    gemm_nt<0><<<dim3(8, 5, BB), 256>>>(TT, DD, NN,
        s1T, NN, (long long)TT * NN,
        fT,  NN, (long long)DD * NN,
        f1,  DD, (long long)TT * DD, nullptr, nullptr, 1);

    // 9) H[bt][h] = relu(sum_d f1[bt,d]*Wh[d,h] + txh[t,h] + bh[h])
    gemm_nt<1><<<dim3(4, 158, 1), 256>>>(BT, HH, DD,
        f1, DD, 0, WhT, 2 * DD, 0, Hb, HH, 0, txh, bh, TT);

    // 10) pred[bt] = dot(H[bt], Wo) + bo
    final_head<<<1260, 256>>>(Hb, Wo, bo, out);
}

// round 4
// speedup vs baseline: 1.3747x; 1.3747x over previous
#include <cuda_runtime.h>
#include <cuda_bf16.h>
#include <cstdint>

// Problem constants
#define BB 32
#define NN 400
#define TT 315
#define DD 512
#define HH 256
#define BT (BB*TT)          // 10080
#define NT (NN*TT)          // 126000

// ---------------- scratch (static device globals; no allocation) -------------
__device__ float g_WhT[HH*2*DD];        // [256][1024]
__device__ float g_TAT[TT*DD];          // [315][512]
__device__ float g_S[BB*NN*TT];         // [32][400][315]
__device__ float g_txh[TT*HH];          // [315][256]
__device__ float g_mv[2*BB];            // mean, rstd per batch
__device__ float g_FWT[BB*HH*NN];       // [32][256][400]
__device__ float g_s1T[BB*TT*NN];       // [32][315][400]
__device__ float g_H[BB*TT*HH];         // [32][315][256]

// ================= helpers ===================================================
__device__ __forceinline__ uint32_t smem_to_u32(const void* p) {
    uint32_t a;
    asm("{ .reg .u64 t; cvta.to.shared.u64 t, %1; cvt.u32.u64 %0, t; }"
        : "=r"(a) : "l"(p));
    return a;
}

#define STS128(r0, r1, r2, r3, smem_addr) \
    asm volatile("st.shared.v4.b32 [%0], {%1, %2, %3, %4};" \
        :: "r"(smem_addr), "r"(r0), "r"(r1), "r"(r2), "r"(r3) : "memory")

// split fp32 pair -> (hi bf16x2, lo bf16x2)
__device__ __forceinline__ void split2(float a0, float a1, uint32_t &h, uint32_t &l)
{
    asm("cvt.rn.satfinite.bf16x2.f32 %0, %1, %2;" : "=r"(h) : "f"(a1), "f"(a0));
    float h0 = __uint_as_float(h << 16);
    float h1 = __uint_as_float(h & 0xffff0000u);
    float l0 = a0 - h0;
    float l1 = a1 - h1;
    asm("cvt.rn.satfinite.bf16x2.f32 %0, %1, %2;" : "=r"(l) : "f"(l1), "f"(l0));
}

__device__ __forceinline__ void ldsm_x4(uint32_t* r, uint32_t addr) {
    asm volatile("ldmatrix.sync.aligned.m8n8.x4.shared.b16 {%0,%1,%2,%3}, [%4];"
        : "=r"(r[0]), "=r"(r[1]), "=r"(r[2]), "=r"(r[3]) : "r"(addr));
}

__device__ __forceinline__ void mma16816(float* c, const uint32_t* a, uint32_t b0, uint32_t b1) {
    asm volatile(
        "mma.sync.aligned.m16n8k16.row.col.f32.bf16.bf16.f32 "
        "{%0,%1,%2,%3}, {%4,%5,%6,%7}, {%8,%9}, {%0,%1,%2,%3};"
        : "+f"(c[0]), "+f"(c[1]), "+f"(c[2]), "+f"(c[3])
        : "r"(a[0]), "r"(a[1]), "r"(a[2]), "r"(a[3]), "r"(b0), "r"(b1));
}

// ================= HMMA bf16-split NT GEMM ===================================
// C[m,n] = sum_k A[m,k]*B[n,k]  (fp32 in/out, bf16 hi/lo split, 3 MMAs)
// CTA 128(M) x 64(N), BK=32 fp32 per stage, double buffered.
// EPI==1: C = relu(acc + aux[gm*N + gn] + bias[gn])

#define AS 80                  // smem bytes per row (64B data + 16B pad)
#define APL (128*AS)           // 10240: one A plane
#define BPL (64*AS)            // 5120:  one B plane
#define STG_SZ (2*APL + 2*BPL) // 30720
#define HG_SMEM (2*STG_SZ)     // 61440

template<int EPI>
__global__ void __launch_bounds__(256, 2) hgemm(
    int M, int N, int K,
    const float* __restrict__ A, int lda, long long sA,
    const float* __restrict__ B, int ldb, long long sB,
    float* __restrict__ C, int ldc, long long sC,
    const float* __restrict__ aux, const float* __restrict__ bias)
{
    extern __shared__ char smem[];
    uint32_t sb = smem_to_u32(smem);
    int tid = threadIdx.x, lane = tid & 31, wid = tid >> 5;

    A += (long long)blockIdx.z * sA;
    B += (long long)blockIdx.z * sB;
    C += (long long)blockIdx.z * sC;
    int m0 = blockIdx.y * 128, n0 = blockIdx.x * 64;

    // global-load mapping
    const int arow = tid >> 1, abase = (tid & 1) * 16;   // 16 k-floats per thread
    const bool aok = (m0 + arow) < M;
    const float* Arow = A + (size_t)(m0 + arow) * lda;
    const int brow = tid >> 2, bbase = (tid & 3) * 8;    // 8 k-floats per thread
    const bool bok = (n0 + brow) < N;
    const float* Brow = B + (size_t)(n0 + brow) * ldb;

    float acc[2][4][4];
    #pragma unroll
    for (int mi = 0; mi < 2; mi++)
        #pragma unroll
        for (int ni = 0; ni < 4; ni++)
            #pragma unroll
            for (int j = 0; j < 4; j++) acc[mi][ni][j] = 0.f;

    const int nst = (K + 31) >> 5;
    float apf[16], bpf[8];

    auto loadg = [&](int st) {
        int k0 = st << 5;
        #pragma unroll
        for (int g = 0; g < 4; g++) {
            int kg = k0 + abase + g * 4;
            float4 v = make_float4(0.f, 0.f, 0.f, 0.f);
            if (aok && kg < K) v = *(const float4*)(Arow + kg);
            apf[g*4+0] = v.x; apf[g*4+1] = v.y; apf[g*4+2] = v.z; apf[g*4+3] = v.w;
        }
        #pragma unroll
        for (int g = 0; g < 2; g++) {
            int kg = k0 + bbase + g * 4;
            float4 v = make_float4(0.f, 0.f, 0.f, 0.f);
            if (bok && kg < K) v = *(const float4*)(Brow + kg);
            bpf[g*4+0] = v.x; bpf[g*4+1] = v.y; bpf[g*4+2] = v.z; bpf[g*4+3] = v.w;
        }
    };

    auto stores = [&](int buf) {
        uint32_t baseA = sb + buf * STG_SZ;
        uint32_t baseB = baseA + 2 * APL;
        #pragma unroll
        for (int g2 = 0; g2 < 2; g2++) {          // two 8-float groups for A
            uint32_t h[4], l[4];
            #pragma unroll
            for (int j = 0; j < 4; j++)
                split2(apf[g2*8 + 2*j], apf[g2*8 + 2*j + 1], h[j], l[j]);
            uint32_t off = (uint32_t)(arow * AS + (abase + g2 * 8) * 2);
            STS128(h[0], h[1], h[2], h[3], baseA + off);
            STS128(l[0], l[1], l[2], l[3], baseA + APL + off);
        }
        {
            uint32_t h[4], l[4];
            #pragma unroll
            for (int j = 0; j < 4; j++)
                split2(bpf[2*j], bpf[2*j + 1], h[j], l[j]);
            uint32_t off = (uint32_t)(brow * AS + bbase * 2);
            STS128(h[0], h[1], h[2], h[3], baseB + off);
            STS128(l[0], l[1], l[2], l[3], baseB + BPL + off);
        }
    };

    const int wm = (wid & 3) * 32;   // warp M offset
    const int wn = (wid >> 2) * 32;  // warp N offset
    const int lrow = lane & 15;
    const int lkof = (lane >> 4) * 8;

    auto compute = [&](int buf) {
        uint32_t baseAhi = sb + buf * STG_SZ;
        uint32_t baseAlo = baseAhi + APL;
        uint32_t baseBhi = baseAhi + 2 * APL;
        uint32_t baseBlo = baseBhi + BPL;
        #pragma unroll
        for (int ks = 0; ks < 2; ks++) {
            uint32_t kb = (uint32_t)((ks * 16 + lkof) * 2);
            uint32_t ahi[2][4], alo[2][4], bhi[2][4], blo[2][4];
            #pragma unroll
            for (int mi = 0; mi < 2; mi++) {
                uint32_t off = (uint32_t)((wm + mi * 16 + lrow) * AS) + kb;
                ldsm_x4(ahi[mi], baseAhi + off);
                ldsm_x4(alo[mi], baseAlo + off);
            }
            #pragma unroll
            for (int np = 0; np < 2; np++) {
                uint32_t off = (uint32_t)((wn + np * 16 + lrow) * AS) + kb;
                ldsm_x4(bhi[np], baseBhi + off);   // B is [n][k]: non-trans gives
                ldsm_x4(blo[np], baseBlo + off);   // the col-major k-pair fragment
            }
            #pragma unroll
            for (int mi = 0; mi < 2; mi++)
                #pragma unroll
                for (int ni = 0; ni < 4; ni++) {
                    int np = ni >> 1, sel = ni & 1;
                    uint32_t bh0 = bhi[np][sel], bh1 = bhi[np][2 + sel];
                    uint32_t bl0 = blo[np][sel], bl1 = blo[np][2 + sel];
                    mma16816(acc[mi][ni], ahi[mi], bh0, bh1);
                    mma16816(acc[mi][ni], ahi[mi], bl0, bl1);
                    mma16816(acc[mi][ni], alo[mi], bh0, bh1);
                }
        }
    };

    loadg(0);
    stores(0);
    __syncthreads();
    for (int c = 0; c < nst; c++) {
        if (c + 1 < nst) loadg(c + 1);
        compute(c & 1);
        if (c + 1 < nst) stores((c + 1) & 1);
        __syncthreads();
    }

    // epilogue
    #pragma unroll
    for (int mi = 0; mi < 2; mi++) {
        #pragma unroll
        for (int ni = 0; ni < 4; ni++) {
            int gm = m0 + wm + mi * 16 + (lane >> 2);
            int gn = n0 + wn + ni * 8 + (lane & 3) * 2;
            float* cc = acc[mi][ni];
            #pragma unroll
            for (int half = 0; half < 2; half++) {
                int r = gm + half * 8;
                if (r < M) {
                    #pragma unroll
                    for (int j = 0; j < 2; j++) {
                        int col = gn + j;
                        if (col < N) {
                            float v = cc[half * 2 + j];
                            if (EPI == 1)
                                v = fmaxf(v + aux[(size_t)r * N + col] + bias[col], 0.f);
                            C[(size_t)r * ldc + col] = v;
                        }
                    }
                }
            }
        }
    }
}

// ---------------- generic 32x32 tiled transpose: out[c][r] = in[r][c] --------
__global__ void transpose_k(const float* __restrict__ in, float* __restrict__ out,
                            int R, int C)
{
    __shared__ float tile[32][33];
    int c0 = blockIdx.x * 32, r0 = blockIdx.y * 32;
    int x = threadIdx.x, y = threadIdx.y;
    #pragma unroll
    for (int j = 0; j < 32; j += 8) {
        int r = r0 + y + j, c = c0 + x;
        tile[y + j][x] = (r < R && c < C) ? in[(size_t)r * C + c] : 0.f;
    }
    __syncthreads();
    #pragma unroll
    for (int j = 0; j < 32; j += 8) {
        int c = c0 + y + j, r = r0 + x;
        if (c < C && r < R) out[(size_t)c * R + r] = tile[x][y + j];
    }
}

// ---------------- per-batch instance-norm stats ------------------------------
__global__ void stats_k(const float* __restrict__ s, float* __restrict__ mv)
{
    int b = blockIdx.x;
    const float* sb = s + (size_t)b * NT;
    float sum = 0.f, sq = 0.f;
    for (int i = threadIdx.x; i < NT; i += 256) {
        float x = sb[i];
        sum += x; sq += x * x;
    }
    __shared__ float ssum[256], ssq[256];
    ssum[threadIdx.x] = sum; ssq[threadIdx.x] = sq;
    __syncthreads();
    for (int o = 128; o > 0; o >>= 1) {
        if (threadIdx.x < o) {
            ssum[threadIdx.x] += ssum[threadIdx.x + o];
            ssq[threadIdx.x]  += ssq[threadIdx.x + o];
        }
        __syncthreads();
    }
    if (threadIdx.x == 0) {
        float m = ssum[0] / (float)NT;
        float var = ssq[0] / (float)NT - m * m;
        mv[2 * b] = m;
        mv[2 * b + 1] = rsqrtf(var + 1e-5f);
    }
}

// ---------------- Sinkhorn: 4-CTA cluster per batch, E resident in SMEM ------
#define SK_NW 8
#define SK_THREADS 256
#define RPC 100
#define TP  317

#define OFF_E    0
#define OFF_V    (RPC*TP)
#define OFF_U    (OFF_V + 320)
#define OFF_WACC (OFF_U + 128)
#define OFF_RECV (OFF_WACC + SK_NW*TP)
#define SK_FLOATS (OFF_RECV + 2*4*TP)
#define SK_SMEM  (SK_FLOATS*4)

__global__ void __cluster_dims__(4, 1, 1) sinkhorn_kernel(
    const float* __restrict__ s, const float* __restrict__ gamma,
    const float* __restrict__ beta, const float* __restrict__ mv,
    float* __restrict__ s1T)
{
    extern __shared__ float sm[];
    float* E    = sm + OFF_E;
    float* vS   = sm + OFF_V;
    float* uS   = sm + OFF_U;
    float* wacc = sm + OFF_WACC;
    float* recv = sm + OFF_RECV;

    int b = blockIdx.x >> 2;
    int rank = blockIdx.x & 3;
    int tid = threadIdx.x, wid = tid >> 5, lane = tid & 31;
    int rowbase = rank * RPC;

    float m = mv[2 * b], rstd = mv[2 * b + 1];
    float g = gamma[0] * rstd, be = beta[0];
    const float* sb = s + (size_t)b * NT + (size_t)rowbase * TT;

    for (int i = tid; i < RPC * TT; i += SK_THREADS) {
        int r = i / TT, c = i - r * TT;
        E[r * TP + c] = __expf(g * (sb[i] - m) + be);
    }
    for (int c = tid; c < TT; c += SK_THREADS) vS[c] = 1.f;
    __syncthreads();

    for (int it = 0; it < 100; ++it) {
        int par = it & 1;
        float vv[10];
        #pragma unroll
        for (int k = 0; k < 10; k++) {
            int c = lane + 32 * k;
            vv[k] = (c < TT) ? vS[c] : 0.f;
        }
        float cacc[10];
        #pragma unroll
        for (int k = 0; k < 10; k++) cacc[k] = 0.f;

        for (int r = wid; r < RPC; r += SK_NW) {
            const float* Er = E + r * TP;
            float e[10];
            float dot = 0.f;
            #pragma unroll
            for (int k = 0; k < 10; k++) {
                int c = lane + 32 * k;
                e[k] = (c < TT) ? Er[c] : 0.f;
                dot += e[k] * vv[k];
            }
            #pragma unroll
            for (int o = 16; o > 0; o >>= 1)
                dot += __shfl_xor_sync(0xffffffffu, dot, o);
            float uu = 1.f / dot;
            if (lane == 0) uS[r] = uu;
            #pragma unroll
            for (int k = 0; k < 10; k++) cacc[k] += uu * e[k];
        }
        #pragma unroll
        for (int k = 0; k < 10; k++) {
            int c = lane + 32 * k;
            if (c < TT) wacc[wid * TP + c] = cacc[k];
        }
        __syncthreads();

        for (int c = tid; c < TT; c += SK_THREADS) {
            float p = 0.f;
            #pragma unroll
            for (int w = 0; w < SK_NW; w++) p += wacc[w * TP + c];
            float* dst = recv + (par * 4 + rank) * TP + c;
            uint32_t laddr = (uint32_t)__cvta_generic_to_shared(dst);
            #pragma unroll
            for (int cta = 0; cta < 4; cta++) {
                uint32_t raddr;
                asm volatile("mapa.shared::cluster.u32 %0, %1, %2;"
                             : "=r"(raddr) : "r"(laddr), "r"(cta));
                asm volatile("st.shared::cluster.f32 [%0], %1;"
                             :: "r"(raddr), "f"(p) : "memory");
            }
        }
        asm volatile("barrier.cluster.arrive.aligned;" ::: "memory");
        asm volatile("barrier.cluster.wait.aligned;" ::: "memory");

        for (int c = tid; c < TT; c += SK_THREADS) {
            float sum = recv[(par * 4 + 0) * TP + c] + recv[(par * 4 + 1) * TP + c]
                      + recv[(par * 4 + 2) * TP + c] + recv[(par * 4 + 3) * TP + c];
            vS[c] = 1.f / sum;
        }
        __syncthreads();
    }

    float* outp = s1T + (size_t)b * TT * NN;
    for (int t = wid; t < TT; t += SK_NW) {
        float vt = vS[t];
        #pragma unroll
        for (int j = 0; j < 4; j++) {
            int n = lane + 32 * j;
            if (n < RPC)
                outp[(size_t)t * NN + rowbase + n] = E[n * TP + t] * uS[n] * vt;
        }
    }
}

// ---------------- final head: pred[bt] = dot(h[bt,:], Wo) + bo ---------------
__global__ void final_head(const float* __restrict__ h, const float* __restrict__ Wo,
                           const float* __restrict__ bo, float* __restrict__ out)
{
    int row = blockIdx.x * 8 + (threadIdx.x >> 5);
    int lane = threadIdx.x & 31;
    if (row >= BT) return;
    const float* hr = h + (size_t)row * HH;
    float acc = 0.f;
    #pragma unroll
    for (int k = 0; k < HH / 32; k++)
        acc += hr[lane + 32 * k] * Wo[lane + 32 * k];
    #pragma unroll
    for (int o = 16; o > 0; o >>= 1)
        acc += __shfl_xor_sync(0xffffffffu, acc, o);
    if (lane == 0) out[row] = acc + bo[0];
}

// ---------------- launcher ---------------------------------------------------
extern "C" void kernel_launch(void* const* d_in, const int* in_sizes, int n_in,
                              void* d_out, int out_size)
{
    const float* features = (const float*)d_in[0];
    const float* text     = (const float*)d_in[1];
    const float* Amat     = (const float*)d_in[2];
    const float* gamma    = (const float*)d_in[3];
    const float* beta     = (const float*)d_in[4];
    const float* Wh       = (const float*)d_in[5];
    const float* bh       = (const float*)d_in[6];
    const float* Wo       = (const float*)d_in[7];
    const float* bo       = (const float*)d_in[8];
    float* out = (float*)d_out;

    float *WhT, *TAT, *S, *txh, *mv, *FWT, *s1T, *Hb;
    cudaGetSymbolAddress((void**)&WhT, g_WhT);
    cudaGetSymbolAddress((void**)&TAT, g_TAT);
    cudaGetSymbolAddress((void**)&S,   g_S);
    cudaGetSymbolAddress((void**)&txh, g_txh);
    cudaGetSymbolAddress((void**)&mv,  g_mv);
    cudaGetSymbolAddress((void**)&FWT, g_FWT);
    cudaGetSymbolAddress((void**)&s1T, g_s1T);
    cudaGetSymbolAddress((void**)&Hb,  g_H);

    cudaFuncSetAttribute(sinkhorn_kernel,
                         cudaFuncAttributeMaxDynamicSharedMemorySize, SK_SMEM);
    cudaFuncSetAttribute(hgemm<0>,
                         cudaFuncAttributeMaxDynamicSharedMemorySize, HG_SMEM);
    cudaFuncSetAttribute(hgemm<1>,
                         cudaFuncAttributeMaxDynamicSharedMemorySize, HG_SMEM);

    // 1) WhT[h][c] = Wh[c][h]   (1024x256 -> 256x1024)
    transpose_k<<<dim3(8, 32, 1), dim3(32, 8)>>>(Wh, WhT, 2 * DD, HH);

    // 2) TAT[t][d] = sum_e text[t,e]*A[d,e]   M=315,N=512,K=512
    hgemm<0><<<dim3(8, 3, 1), 256, HG_SMEM>>>(TT, DD, DD,
        text, DD, 0, Amat, DD, 0, TAT, DD, 0, nullptr, nullptr);

    // 3) S[bn][t] = sum_d features[bn,d]*TAT[t,d]   M=12800,N=315,K=512
    hgemm<0><<<dim3(5, 100, 1), 256, HG_SMEM>>>(BB * NN, TT, DD,
        features, DD, 0, TAT, DD, 0, S, TT, 0, nullptr, nullptr);

    // 4) txh[t][h] = sum_d text[t,d]*WhT[h][512+d]   M=315,N=256,K=512
    hgemm<0><<<dim3(4, 3, 1), 256, HG_SMEM>>>(TT, HH, DD,
        text, DD, 0, WhT + DD, 2 * DD, 0, txh, HH, 0, nullptr, nullptr);

    // 5) instance-norm stats per batch
    stats_k<<<BB, 256>>>(S, mv);

    // 6) FWT[b][h][n] = sum_d WhT[h][d]*features[b][n][d]   M=256,N=400,K=512
    hgemm<0><<<dim3(7, 2, BB), 256, HG_SMEM>>>(HH, NN, DD,
        WhT, 2 * DD, 0,
        features, DD, (long long)NN * DD,
        FWT, NN, (long long)HH * NN, nullptr, nullptr);

    // 7) Sinkhorn -> s1T[b][t][n]
    sinkhorn_kernel<<<BB * 4, SK_THREADS, SK_SMEM>>>(S, gamma, beta, mv, s1T);

    // 8) H[b][t][h] = relu(sum_n s1T[b][t][n]*FWT[b][h][n] + txh[t][h] + bh[h])
    hgemm<1><<<dim3(4, 3, BB), 256, HG_SMEM>>>(TT, HH, NN,
        s1T, NN, (long long)TT * NN,
        FWT, NN, (long long)HH * NN,
        Hb,  HH, (long long)TT * HH, txh, bh);

    // 9) pred[bt] = dot(H[bt], Wo) + bo
    final_head<<<1260, 256>>>(Hb, Wo, bo, out);
}